// round 15
// baseline (speedup 1.0000x reference)
#include <cuda_runtime.h>
#include <cuda_bf16.h>
#include <cstdint>

#define HH 128
#define WW_ 256
#define CDIM 192
#define HDIM 32
#define HIDDEN 768
#define MROWS 131072
#define SHIFT 4
#define PGRID 304

__device__ __nv_bfloat16 g_xw [(size_t)MROWS*CDIM];
__device__ __nv_bfloat16 g_x1w[(size_t)MROWS*CDIM];
__device__ __nv_bfloat16 g_qb [(size_t)MROWS*CDIM];
__device__ __nv_bfloat16 g_kvb[(size_t)MROWS*2*CDIM];
__device__ __nv_bfloat16 g_ao [(size_t)MROWS*CDIM];
__device__ float         g_xo [(size_t)MROWS*CDIM];
__device__ __nv_bfloat16 g_xn2[(size_t)MROWS*CDIM];
__device__ __nv_bfloat16 g_hb [(size_t)MROWS*HIDDEN];
__device__ __nv_bfloat16 g_wq [CDIM*CDIM];
__device__ __nv_bfloat16 g_wkv[2*CDIM*CDIM];
__device__ __nv_bfloat16 g_wp [CDIM*CDIM];
__device__ __nv_bfloat16 g_wf1[HIDDEN*CDIM];
__device__ __nv_bfloat16 g_wf2[CDIM*HIDDEN];

__device__ __forceinline__ uint32_t smem_u32(const void* p){
    uint32_t r; asm("{ .reg .u64 t; cvta.to.shared.u64 t, %1; cvt.u32.u64 %0, t; }":"=r"(r):"l"(p)); return r;
}
__device__ __forceinline__ int win_src_row(int r){
    int b_=r>>6, t=r&63, b=b_>>9, wid=b_&511;
    int h=(((wid>>5)<<3)+(t>>3)+SHIFT)&(HH-1);
    int w=(((wid&31)<<3)+(t&7)+SHIFT)&(WW_-1);
    return (b<<15)+(h<<8)+w;
}
__device__ __forceinline__ float warp_sum(float v){
#pragma unroll
    for(int o=16;o>0;o>>=1) v+=__shfl_xor_sync(0xffffffffu,v,o);
    return v;
}
__device__ __forceinline__ float gelu_exact(float v){ return 0.5f*v*(1.0f+erff(v*0.70710678118654752f)); }
__device__ __forceinline__ uint32_t bf2pack(float lo,float hi){
    uint32_t r; asm("cvt.rn.bf16x2.f32 %0, %1, %2;":"=r"(r):"f"(hi),"f"(lo)); return r;
}
__device__ __forceinline__ void cp_async16(uint32_t dst, const void* src){
    asm volatile("cp.async.cg.shared.global [%0], [%1], 16;"::"r"(dst),"l"(src):"memory");
}
__device__ __forceinline__ void cp_commit(){ asm volatile("cp.async.commit_group;":::"memory"); }
template<int N> __device__ __forceinline__ void cp_wait(){ asm volatile("cp.async.wait_group %0;"::"n"(N):"memory"); }

// ---------------------------------------------------------------------------
// Fused weight prep
// ---------------------------------------------------------------------------
__global__ void wt_transpose_all(const float* __restrict__ q_w, const float* __restrict__ kv_w,
                                 const float* __restrict__ proj_w, const float* __restrict__ fc1_w,
                                 const float* __restrict__ fc2_w,
                                 __nv_bfloat16* __restrict__ wq, __nv_bfloat16* __restrict__ wkv,
                                 __nv_bfloat16* __restrict__ wp, __nv_bfloat16* __restrict__ wf1,
                                 __nv_bfloat16* __restrict__ wf2){
    int i = blockIdx.x*256+threadIdx.x;
    const float* s; __nv_bfloat16* d; int K, N;
    if      (i < 36864)  { s=q_w;    d=wq;  K=CDIM;   N=CDIM;   }
    else if (i < 110592) { s=kv_w;   d=wkv; K=CDIM;   N=2*CDIM; i-=36864;  }
    else if (i < 147456) { s=proj_w; d=wp;  K=CDIM;   N=CDIM;   i-=110592; }
    else if (i < 294912) { s=fc1_w;  d=wf1; K=CDIM;   N=HIDDEN; i-=147456; }
    else if (i < 442368) { s=fc2_w;  d=wf2; K=HIDDEN; N=CDIM;   i-=294912; }
    else return;
    int n=i/K, k=i-n*K;
    d[i] = __float2bfloat16(s[(size_t)k*N+n]);
}

__global__ void ln1_gather_kernel(const float* __restrict__ x, const float* __restrict__ x1,
                                  const float* __restrict__ g, const float* __restrict__ bb,
                                  __nv_bfloat16* __restrict__ xw, __nv_bfloat16* __restrict__ x1w){
    int r=blockIdx.x, src=win_src_row(r), t=threadIdx.x;
    float v0=x[(size_t)src*CDIM+t], v1=x1[(size_t)src*CDIM+t];
    float s0=warp_sum(v0), q0=warp_sum(v0*v0), s1=warp_sum(v1), q1=warp_sum(v1*v1);
    __shared__ float red[4][6];
    int wp=t>>5, ln=t&31;
    if(ln==0){ red[0][wp]=s0; red[1][wp]=q0; red[2][wp]=s1; red[3][wp]=q1; }
    __syncthreads();
    float S0=0,Q0=0,S1=0,Q1=0;
#pragma unroll
    for(int i=0;i<6;i++){ S0+=red[0][i]; Q0+=red[1][i]; S1+=red[2][i]; Q1+=red[3][i]; }
    const float inv=1.0f/CDIM;
    float m0=S0*inv, m1=S1*inv;
    float r0=rsqrtf(Q0*inv-m0*m0+1e-5f), r1=rsqrtf(Q1*inv-m1*m1+1e-5f);
    float gg=g[t], bv=bb[t];
    xw [(size_t)r*CDIM+t]=__float2bfloat16((v0-m0)*r0*gg+bv);
    x1w[(size_t)r*CDIM+t]=__float2bfloat16((v1-m1)*r1*gg+bv);
}

__global__ void ln2_kernel(const float* __restrict__ x, const float* __restrict__ g,
                           const float* __restrict__ bb, __nv_bfloat16* __restrict__ out){
    int r=blockIdx.x, t=threadIdx.x;
    float v=x[(size_t)r*CDIM+t];
    float s=warp_sum(v), q=warp_sum(v*v);
    __shared__ float red[2][6];
    int wp=t>>5, ln=t&31;
    if(ln==0){ red[0][wp]=s; red[1][wp]=q; }
    __syncthreads();
    float S=0,Q=0;
#pragma unroll
    for(int i=0;i<6;i++){ S+=red[0][i]; Q+=red[1][i]; }
    const float inv=1.0f/CDIM;
    float m=S*inv, rs=rsqrtf(Q*inv-m*m+1e-5f);
    out[(size_t)r*CDIM+t]=__float2bfloat16((v-m)*rs*g[t]+bb[t]);
}

// ---------------------------------------------------------------------------
// Persistent-streaming HMMA bf16 GEMM: C = A @ Bw^T.  BM=128 BN=64 BK=64.
// R15: 128 threads, 4 warps in 2x2, warp tile 64x32 (FLOP/smem-byte 16->21.3,
// A re-read x2 / B re-read x2 = 48KB/chunk vs 64KB). 4-buffer ring,
// prefetch distance 2, one barrier per chunk (R14 scheme, measured best).
// EPI: 0 bias, 1 bias+gelu, 2 bias+scatter+residual, 3 bias+residual.
// ---------------------------------------------------------------------------
#define ABUF 16384
#define BUFB 24576
#define GEMM_SMEM_BYTES (4*BUFB + 1024)

template <int EPI, int OUTBF>
__global__ __launch_bounds__(128)
void gemm_mma(const __nv_bfloat16* __restrict__ A, const __nv_bfloat16* __restrict__ Bw,
              const float* __restrict__ bias, const float* __restrict__ res,
              void* __restrict__ Cv, int M, int N, int K){
    extern __shared__ char dsm[];
    uint32_t base = (smem_u32(dsm)+1023u)&~1023u;

    int tid=threadIdx.x, lane=tid&31, wid=tid>>5;
    int wm=wid&1, wn=wid>>1;           // 2 x 2 warps, warp tile 64x32
    int Nb=N>>6, nch=K>>6;
    int ntiles=(M>>7)*Nb;

    auto stage=[&](int buf,int m0,int n0,int k0){
        uint32_t sA=base+buf*BUFB, sB=sA+ABUF;
#pragma unroll
        for(int l=0;l<8;l++){           // A: 1024 x 16B over 128 thr
            int i=tid+l*128, rr=i>>3, cc=i&7;
            uint32_t off=rr*128+cc*16;
            cp_async16(sA+(off^((off>>3)&0x70)), A+(size_t)(m0+rr)*K+k0+cc*8);
        }
#pragma unroll
        for(int l=0;l<4;l++){           // B: 512 x 16B
            int i=tid+l*128, rr=i>>3, cc=i&7;
            uint32_t off=rr*128+cc*16;
            cp_async16(sB+(off^((off>>3)&0x70)), Bw+(size_t)(n0+rr)*K+k0+cc*8);
        }
        cp_commit();
    };

    int t0=blockIdx.x;
    if(t0>=ntiles) return;

    int st_t=t0, st_c=0, st_buf=0;
    auto stage_next=[&](){
        if(st_t<ntiles){
            int mm=st_t/Nb, nn=st_t-mm*Nb;
            stage(st_buf, mm<<7, nn<<6, st_c<<6);
        } else cp_commit();
        st_buf=(st_buf+1)&3;
        if(++st_c==nch){ st_c=0; st_t+=PGRID; }
    };

    stage_next();
    stage_next();
    int gbuf=0;

    for(int t=t0; t<ntiles; t+=PGRID){
        float acc[4][4][4];
#pragma unroll
        for(int a=0;a<4;a++)
#pragma unroll
            for(int b=0;b<4;b++)
#pragma unroll
                for(int c=0;c<4;c++) acc[a][b][c]=0.0f;

        for(int c=0;c<nch;c++){
            stage_next();
            cp_wait<2>();
            __syncthreads();

            uint32_t sA=base+gbuf*BUFB, sB=sA+ABUF;
#pragma unroll
            for(int kk=0;kk<4;kk++){
                uint32_t af[4][4];
#pragma unroll
                for(int mt=0;mt<4;mt++){
                    int row=wm*64+mt*16+(lane&15);
                    uint32_t off=row*128+kk*32+(lane>>4)*16;
                    off^=((off>>3)&0x70);
                    asm volatile("ldmatrix.sync.aligned.m8n8.x4.shared.b16 {%0,%1,%2,%3}, [%4];"
                        :"=r"(af[mt][0]),"=r"(af[mt][1]),"=r"(af[mt][2]),"=r"(af[mt][3]):"r"(sA+off));
                }
                uint32_t bf[4][2];
#pragma unroll
                for(int nt2=0;nt2<4;nt2++){
                    int rowb=wn*32+nt2*8+(lane&7);
                    uint32_t off=rowb*128+kk*32+((lane>>3)&1)*16;
                    off^=((off>>3)&0x70);
                    asm volatile("ldmatrix.sync.aligned.m8n8.x2.shared.b16 {%0,%1}, [%2];"
                        :"=r"(bf[nt2][0]),"=r"(bf[nt2][1]):"r"(sB+off));
                }
#pragma unroll
                for(int mt=0;mt<4;mt++)
#pragma unroll
                    for(int nt2=0;nt2<4;nt2++)
                        asm volatile("mma.sync.aligned.m16n8k16.row.col.f32.bf16.bf16.f32 "
                            "{%0,%1,%2,%3}, {%4,%5,%6,%7}, {%8,%9}, {%0,%1,%2,%3};"
                            :"+f"(acc[mt][nt2][0]),"+f"(acc[mt][nt2][1]),"+f"(acc[mt][nt2][2]),"+f"(acc[mt][nt2][3])
                            :"r"(af[mt][0]),"r"(af[mt][1]),"r"(af[mt][2]),"r"(af[mt][3]),
                             "r"(bf[nt2][0]),"r"(bf[nt2][1]));
            }
            gbuf=(gbuf+1)&3;
        }

        int m0=(t/Nb)<<7, n0=(t-(t/Nb)*Nb)<<6;
#pragma unroll
        for(int mt=0;mt<4;mt++){
#pragma unroll
            for(int half=0;half<2;half++){
                int row=m0+wm*64+mt*16+(lane>>2)+half*8;
                int orow=(EPI==2)?win_src_row(row):row;
#pragma unroll
                for(int nt2=0;nt2<4;nt2++){
                    int col=n0+wn*32+nt2*8+(lane&3)*2;
                    float v0=acc[mt][nt2][half*2+0]+__ldg(bias+col);
                    float v1=acc[mt][nt2][half*2+1]+__ldg(bias+col+1);
                    if(EPI==1){ v0=gelu_exact(v0); v1=gelu_exact(v1); }
                    if(EPI==2||EPI==3){
                        const float* rp=res+(size_t)orow*N+col;
                        v0+=rp[0]; v1+=rp[1];
                    }
                    if(OUTBF){
                        *(uint32_t*)((__nv_bfloat16*)Cv+(size_t)orow*N+col)=bf2pack(v0,v1);
                    }else{
                        *(float2*)((float*)Cv+(size_t)orow*N+col)=make_float2(v0,v1);
                    }
                }
            }
        }
    }
}

// ---------------------------------------------------------------------------
// Attention: one block per window, 384 thr (6 heads x 64 rows), f32x2 FMA,
// single-pass softmax (scores tiny; mask -100 underflows exp -> 0).
// ---------------------------------------------------------------------------
#define ATTN_SMEM_BYTES 112256

__global__ __launch_bounds__(384)
void attn_kernel(const __nv_bfloat16* __restrict__ q, const __nv_bfloat16* __restrict__ kv,
                 const float* __restrict__ rpb, const float* __restrict__ mask,
                 __nv_bfloat16* __restrict__ ao){
    extern __shared__ char dsm[];
    unsigned long long* K8=(unsigned long long*)dsm;
    unsigned long long* V8=K8+64*96;
    __nv_bfloat16* Ms=(__nv_bfloat16*)(V8+64*96);
    float* Rp=(float*)(Ms+64*66);

    int win=blockIdx.x, tid=threadIdx.x;
    const __nv_bfloat162* kvb=(const __nv_bfloat162*)(kv+(size_t)win*64*384);
    for(int i=tid;i<64*192;i+=384){
        int row=i/192, p=i-row*192;
        float2 f=__bfloat1622float2(kvb[row*192+p]);
        unsigned long long pk;
        asm("mov.b64 %0,{%1,%2};":"=l"(pk):"r"(__float_as_uint(f.x)),"r"(__float_as_uint(f.y)));
        if(p<96) K8[row*96+p]=pk; else V8[row*96+p-96]=pk;
    }
    const float* mg=mask+(size_t)(win&511)*4096;
    for(int i=tid;i<4096;i+=384) Ms[(i>>6)*66+(i&63)]=__float2bfloat16(mg[i]);
    for(int i=tid;i<1350;i+=384) Rp[i]=rpb[i];

    int h=tid/64, t=tid-h*64;
    unsigned long long q2[16];
    {
        const __nv_bfloat162* qp=(const __nv_bfloat162*)(q+((size_t)win*64+t)*CDIM+h*HDIM);
        const float sc=0.17677669529663688f;
#pragma unroll
        for(int d=0;d<16;d++){
            float2 f=__bfloat1622float2(qp[d]);
            f.x*=sc; f.y*=sc;
            asm("mov.b64 %0,{%1,%2};":"=l"(q2[d]):"r"(__float_as_uint(f.x)),"r"(__float_as_uint(f.y)));
        }
    }
    __syncthreads();

    int i1=t>>3, j1=t&7, kb=h*16;
    unsigned long long od[16];
#pragma unroll
    for(int d=0;d<16;d++) od[d]=0ULL;
    float sum=0.0f;

    for(int m=0;m<64;m++){
        const unsigned long long* kp=K8+m*96+kb;
        unsigned long long a0=0,a1=0,a2=0,a3=0;
#pragma unroll
        for(int d=0;d<16;d+=4){
            asm("fma.rn.f32x2 %0, %1, %2, %0;":"+l"(a0):"l"(q2[d+0]),"l"(kp[d+0]));
            asm("fma.rn.f32x2 %0, %1, %2, %0;":"+l"(a1):"l"(q2[d+1]),"l"(kp[d+1]));
            asm("fma.rn.f32x2 %0, %1, %2, %0;":"+l"(a2):"l"(q2[d+2]),"l"(kp[d+2]));
            asm("fma.rn.f32x2 %0, %1, %2, %0;":"+l"(a3):"l"(q2[d+3]),"l"(kp[d+3]));
        }
        uint32_t lo,hi; float s;
        asm("mov.b64 {%0,%1}, %2;":"=r"(lo),"=r"(hi):"l"(a0)); s =__uint_as_float(lo)+__uint_as_float(hi);
        asm("mov.b64 {%0,%1}, %2;":"=r"(lo),"=r"(hi):"l"(a1)); s+=__uint_as_float(lo)+__uint_as_float(hi);
        asm("mov.b64 {%0,%1}, %2;":"=r"(lo),"=r"(hi):"l"(a2)); s+=__uint_as_float(lo)+__uint_as_float(hi);
        asm("mov.b64 {%0,%1}, %2;":"=r"(lo),"=r"(hi):"l"(a3)); s+=__uint_as_float(lo)+__uint_as_float(hi);

        int ridx=(i1-(m>>3)+7)*15+(j1-(m&7)+7);
        s += Rp[ridx*6+h] + __bfloat162float(Ms[t*66+m]);
        float e=__expf(s);
        sum+=e;
        unsigned long long e2;
        asm("mov.b64 %0,{%1,%1};":"=l"(e2):"r"(__float_as_uint(e)));
        const unsigned long long* vp=V8+m*96+kb;
#pragma unroll
        for(int d=0;d<16;d++)
            asm("fma.rn.f32x2 %0, %1, %2, %0;":"+l"(od[d]):"l"(e2),"l"(vp[d]));
    }
    float inv=1.0f/sum;
    __nv_bfloat162* orow=(__nv_bfloat162*)(ao+((size_t)win*64+t)*CDIM+h*HDIM);
#pragma unroll
    for(int d=0;d<16;d++){
        uint32_t lo,hi;
        asm("mov.b64 {%0,%1}, %2;":"=r"(lo),"=r"(hi):"l"(od[d]));
        orow[d]=__floats2bfloat162_rn(__uint_as_float(lo)*inv,__uint_as_float(hi)*inv);
    }
}

extern "C" void kernel_launch(void* const* d_in, const int* in_sizes, int n_in,
                              void* d_out, int out_size){
    const float* x     =(const float*)d_in[0];
    const float* x1    =(const float*)d_in[1];
    const float* mask  =(const float*)d_in[2];
    const float* n1g   =(const float*)d_in[3];
    const float* n1b   =(const float*)d_in[4];
    const float* q_w   =(const float*)d_in[5];
    const float* q_b   =(const float*)d_in[6];
    const float* kv_w  =(const float*)d_in[7];
    const float* kv_b  =(const float*)d_in[8];
    const float* rpb   =(const float*)d_in[9];
    const float* proj_w=(const float*)d_in[10];
    const float* proj_b=(const float*)d_in[11];
    const float* n2g   =(const float*)d_in[12];
    const float* n2b   =(const float*)d_in[13];
    const float* fc1_w =(const float*)d_in[14];
    const float* fc1_b =(const float*)d_in[15];
    const float* fc2_w =(const float*)d_in[16];
    const float* fc2_b =(const float*)d_in[17];

    __nv_bfloat16 *xw,*x1w,*qb,*kvb,*ao,*xn2,*hb,*wq,*wkv,*wp,*wf1,*wf2;
    float* xo;
    cudaGetSymbolAddress((void**)&xw, g_xw);  cudaGetSymbolAddress((void**)&x1w,g_x1w);
    cudaGetSymbolAddress((void**)&qb, g_qb);  cudaGetSymbolAddress((void**)&kvb,g_kvb);
    cudaGetSymbolAddress((void**)&ao, g_ao);  cudaGetSymbolAddress((void**)&xo, g_xo);
    cudaGetSymbolAddress((void**)&xn2,g_xn2); cudaGetSymbolAddress((void**)&hb, g_hb);
    cudaGetSymbolAddress((void**)&wq, g_wq);  cudaGetSymbolAddress((void**)&wkv,g_wkv);
    cudaGetSymbolAddress((void**)&wp, g_wp);  cudaGetSymbolAddress((void**)&wf1,g_wf1);
    cudaGetSymbolAddress((void**)&wf2,g_wf2);

    cudaFuncSetAttribute(gemm_mma<0,1>, cudaFuncAttributeMaxDynamicSharedMemorySize, GEMM_SMEM_BYTES);
    cudaFuncSetAttribute(gemm_mma<1,1>, cudaFuncAttributeMaxDynamicSharedMemorySize, GEMM_SMEM_BYTES);
    cudaFuncSetAttribute(gemm_mma<2,0>, cudaFuncAttributeMaxDynamicSharedMemorySize, GEMM_SMEM_BYTES);
    cudaFuncSetAttribute(gemm_mma<3,0>, cudaFuncAttributeMaxDynamicSharedMemorySize, GEMM_SMEM_BYTES);
    cudaFuncSetAttribute(attn_kernel,   cudaFuncAttributeMaxDynamicSharedMemorySize, ATTN_SMEM_BYTES);

    wt_transpose_all<<<(442368+255)/256,256>>>(q_w, kv_w, proj_w, fc1_w, fc2_w,
                                               wq, wkv, wp, wf1, wf2);

    ln1_gather_kernel<<<MROWS, CDIM>>>(x, x1, n1g, n1b, xw, x1w);

    gemm_mma<0,1><<<PGRID, 128, GEMM_SMEM_BYTES>>>(x1w, wq,  q_b,  nullptr, qb,  MROWS, CDIM,   CDIM);
    gemm_mma<0,1><<<PGRID, 128, GEMM_SMEM_BYTES>>>(xw,  wkv, kv_b, nullptr, kvb, MROWS, 2*CDIM, CDIM);

    attn_kernel<<<2048, 384, ATTN_SMEM_BYTES>>>(qb, kvb, rpb, mask, ao);

    gemm_mma<2,0><<<PGRID, 128, GEMM_SMEM_BYTES>>>(ao,  wp,  proj_b, x,  xo, MROWS, CDIM, CDIM);

    ln2_kernel<<<MROWS, CDIM>>>(xo, n2g, n2b, xn2);

    gemm_mma<1,1><<<PGRID, 128, GEMM_SMEM_BYTES>>>(xn2, wf1, fc1_b, nullptr, hb, MROWS, HIDDEN, CDIM);
    gemm_mma<3,0><<<PGRID, 128, GEMM_SMEM_BYTES>>>(hb,  wf2, fc2_b, xo, (float*)d_out, MROWS, CDIM, HIDDEN);
}

// round 16
// speedup vs baseline: 1.0064x; 1.0064x over previous
#include <cuda_runtime.h>
#include <cuda_bf16.h>
#include <cstdint>

#define HH 128
#define WW_ 256
#define CDIM 192
#define HDIM 32
#define HIDDEN 768
#define MROWS 131072
#define SHIFT 4
#define PGRID 304

__device__ __nv_bfloat16 g_xw [(size_t)MROWS*CDIM];
__device__ __nv_bfloat16 g_x1w[(size_t)MROWS*CDIM];
__device__ __nv_bfloat16 g_qb [(size_t)MROWS*CDIM];
__device__ __nv_bfloat16 g_kvb[(size_t)MROWS*2*CDIM];
__device__ __nv_bfloat16 g_ao [(size_t)MROWS*CDIM];
__device__ float         g_xo [(size_t)MROWS*CDIM];
__device__ __nv_bfloat16 g_xn2[(size_t)MROWS*CDIM];
__device__ __nv_bfloat16 g_hb [(size_t)MROWS*HIDDEN];
__device__ __nv_bfloat16 g_wq [CDIM*CDIM];
__device__ __nv_bfloat16 g_wkv[2*CDIM*CDIM];
__device__ __nv_bfloat16 g_wp [CDIM*CDIM];
__device__ __nv_bfloat16 g_wf1[HIDDEN*CDIM];
__device__ __nv_bfloat16 g_wf2[CDIM*HIDDEN];

__device__ __forceinline__ uint32_t smem_u32(const void* p){
    uint32_t r; asm("{ .reg .u64 t; cvta.to.shared.u64 t, %1; cvt.u32.u64 %0, t; }":"=r"(r):"l"(p)); return r;
}
__device__ __forceinline__ int win_src_row(int r){
    int b_=r>>6, t=r&63, b=b_>>9, wid=b_&511;
    int h=(((wid>>5)<<3)+(t>>3)+SHIFT)&(HH-1);
    int w=(((wid&31)<<3)+(t&7)+SHIFT)&(WW_-1);
    return (b<<15)+(h<<8)+w;
}
__device__ __forceinline__ float warp_sum(float v){
#pragma unroll
    for(int o=16;o>0;o>>=1) v+=__shfl_xor_sync(0xffffffffu,v,o);
    return v;
}
__device__ __forceinline__ float gelu_exact(float v){ return 0.5f*v*(1.0f+erff(v*0.70710678118654752f)); }
__device__ __forceinline__ uint32_t bf2pack(float lo,float hi){
    uint32_t r; asm("cvt.rn.bf16x2.f32 %0, %1, %2;":"=r"(r):"f"(hi),"f"(lo)); return r;
}
__device__ __forceinline__ void cp_async16(uint32_t dst, const void* src){
    asm volatile("cp.async.cg.shared.global [%0], [%1], 16;"::"r"(dst),"l"(src):"memory");
}
__device__ __forceinline__ void cp_commit(){ asm volatile("cp.async.commit_group;":::"memory"); }
template<int N> __device__ __forceinline__ void cp_wait(){ asm volatile("cp.async.wait_group %0;"::"n"(N):"memory"); }

// ---------------------------------------------------------------------------
// Fused weight prep
// ---------------------------------------------------------------------------
__global__ void wt_transpose_all(const float* __restrict__ q_w, const float* __restrict__ kv_w,
                                 const float* __restrict__ proj_w, const float* __restrict__ fc1_w,
                                 const float* __restrict__ fc2_w,
                                 __nv_bfloat16* __restrict__ wq, __nv_bfloat16* __restrict__ wkv,
                                 __nv_bfloat16* __restrict__ wp, __nv_bfloat16* __restrict__ wf1,
                                 __nv_bfloat16* __restrict__ wf2){
    int i = blockIdx.x*256+threadIdx.x;
    const float* s; __nv_bfloat16* d; int K, N;
    if      (i < 36864)  { s=q_w;    d=wq;  K=CDIM;   N=CDIM;   }
    else if (i < 110592) { s=kv_w;   d=wkv; K=CDIM;   N=2*CDIM; i-=36864;  }
    else if (i < 147456) { s=proj_w; d=wp;  K=CDIM;   N=CDIM;   i-=110592; }
    else if (i < 294912) { s=fc1_w;  d=wf1; K=CDIM;   N=HIDDEN; i-=147456; }
    else if (i < 442368) { s=fc2_w;  d=wf2; K=HIDDEN; N=CDIM;   i-=294912; }
    else return;
    int n=i/K, k=i-n*K;
    d[i] = __float2bfloat16(s[(size_t)k*N+n]);
}

__global__ void ln1_gather_kernel(const float* __restrict__ x, const float* __restrict__ x1,
                                  const float* __restrict__ g, const float* __restrict__ bb,
                                  __nv_bfloat16* __restrict__ xw, __nv_bfloat16* __restrict__ x1w){
    int r=blockIdx.x, src=win_src_row(r), t=threadIdx.x;
    float v0=x[(size_t)src*CDIM+t], v1=x1[(size_t)src*CDIM+t];
    float s0=warp_sum(v0), q0=warp_sum(v0*v0), s1=warp_sum(v1), q1=warp_sum(v1*v1);
    __shared__ float red[4][6];
    int wp=t>>5, ln=t&31;
    if(ln==0){ red[0][wp]=s0; red[1][wp]=q0; red[2][wp]=s1; red[3][wp]=q1; }
    __syncthreads();
    float S0=0,Q0=0,S1=0,Q1=0;
#pragma unroll
    for(int i=0;i<6;i++){ S0+=red[0][i]; Q0+=red[1][i]; S1+=red[2][i]; Q1+=red[3][i]; }
    const float inv=1.0f/CDIM;
    float m0=S0*inv, m1=S1*inv;
    float r0=rsqrtf(Q0*inv-m0*m0+1e-5f), r1=rsqrtf(Q1*inv-m1*m1+1e-5f);
    float gg=g[t], bv=bb[t];
    xw [(size_t)r*CDIM+t]=__float2bfloat16((v0-m0)*r0*gg+bv);
    x1w[(size_t)r*CDIM+t]=__float2bfloat16((v1-m1)*r1*gg+bv);
}

__global__ void ln2_kernel(const float* __restrict__ x, const float* __restrict__ g,
                           const float* __restrict__ bb, __nv_bfloat16* __restrict__ out){
    int r=blockIdx.x, t=threadIdx.x;
    float v=x[(size_t)r*CDIM+t];
    float s=warp_sum(v), q=warp_sum(v*v);
    __shared__ float red[2][6];
    int wp=t>>5, ln=t&31;
    if(ln==0){ red[0][wp]=s; red[1][wp]=q; }
    __syncthreads();
    float S=0,Q=0;
#pragma unroll
    for(int i=0;i<6;i++){ S+=red[0][i]; Q+=red[1][i]; }
    const float inv=1.0f/CDIM;
    float m=S*inv, rs=rsqrtf(Q*inv-m*m+1e-5f);
    out[(size_t)r*CDIM+t]=__float2bfloat16((v-m)*rs*g[t]+bb[t]);
}

// ---------------------------------------------------------------------------
// Persistent-streaming HMMA bf16 GEMM: C = A @ Bw^T.  BM=128 BN=64 BK=64,
// 256 thr, 8 warps (4x2), warp tile 32x32 (R14 config, measured best).
// R16: B fragments loaded with ldmatrix.x4 over nt-PAIRS (2 instr/kk vs 4,
// same registers) -- halves B LDSM issue count.
// EPI: 0 bias, 1 bias+gelu, 2 bias+scatter+residual, 3 bias+residual.
// ---------------------------------------------------------------------------
#define ABUF 16384
#define BUFB 24576
#define GEMM_SMEM_BYTES (4*BUFB + 1024)

template <int EPI, int OUTBF>
__global__ __launch_bounds__(256)
void gemm_mma(const __nv_bfloat16* __restrict__ A, const __nv_bfloat16* __restrict__ Bw,
              const float* __restrict__ bias, const float* __restrict__ res,
              void* __restrict__ Cv, int M, int N, int K){
    extern __shared__ char dsm[];
    uint32_t base = (smem_u32(dsm)+1023u)&~1023u;

    int tid=threadIdx.x, lane=tid&31, wid=tid>>5;
    int wm=wid&3, wn=wid>>2;
    int Nb=N>>6, nch=K>>6;
    int ntiles=(M>>7)*Nb;

    auto stage=[&](int buf,int m0,int n0,int k0){
        uint32_t sA=base+buf*BUFB, sB=sA+ABUF;
#pragma unroll
        for(int l=0;l<4;l++){           // A: 1024 x 16B
            int i=tid+l*256, rr=i>>3, cc=i&7;
            uint32_t off=rr*128+cc*16;
            cp_async16(sA+(off^((off>>3)&0x70)), A+(size_t)(m0+rr)*K+k0+cc*8);
        }
#pragma unroll
        for(int l=0;l<2;l++){           // B: 512 x 16B
            int i=tid+l*256, rr=i>>3, cc=i&7;
            uint32_t off=rr*128+cc*16;
            cp_async16(sB+(off^((off>>3)&0x70)), Bw+(size_t)(n0+rr)*K+k0+cc*8);
        }
        cp_commit();
    };

    int t0=blockIdx.x;
    if(t0>=ntiles) return;

    int st_t=t0, st_c=0, st_buf=0;
    auto stage_next=[&](){
        if(st_t<ntiles){
            int mm=st_t/Nb, nn=st_t-mm*Nb;
            stage(st_buf, mm<<7, nn<<6, st_c<<6);
        } else cp_commit();
        st_buf=(st_buf+1)&3;
        if(++st_c==nch){ st_c=0; st_t+=PGRID; }
    };

    stage_next();
    stage_next();
    int gbuf=0;

    // B x4 ldmatrix lane addressing (constant per thread, hoisted):
    // quad q=lane>>3: nt_local=q>>1, koff16=(q&1). row = wn*32 + (ntbase+nt_local)*8 + (lane&7)
    int bq_row_off = ((lane>>4)&1)*8 + (lane&7);   // within nt-pair: nt_local*8 + r
    int bq_k16     = (lane>>3)&1;                  // 16B k-offset selector

    for(int t=t0; t<ntiles; t+=PGRID){
        float acc[2][4][4];
#pragma unroll
        for(int a=0;a<2;a++)
#pragma unroll
            for(int b=0;b<4;b++)
#pragma unroll
                for(int c=0;c<4;c++) acc[a][b][c]=0.0f;

        for(int c=0;c<nch;c++){
            stage_next();
            cp_wait<2>();
            __syncthreads();

            uint32_t sA=base+gbuf*BUFB, sB=sA+ABUF;
#pragma unroll
            for(int kk=0;kk<4;kk++){
                uint32_t af[2][4];
#pragma unroll
                for(int mt=0;mt<2;mt++){
                    int row=wm*32+mt*16+(lane&15);
                    uint32_t off=row*128+kk*32+(lane>>4)*16;
                    off^=((off>>3)&0x70);
                    asm volatile("ldmatrix.sync.aligned.m8n8.x4.shared.b16 {%0,%1,%2,%3}, [%4];"
                        :"=r"(af[mt][0]),"=r"(af[mt][1]),"=r"(af[mt][2]),"=r"(af[mt][3]):"r"(sA+off));
                }
                uint32_t bf[4][2];
#pragma unroll
                for(int np=0;np<2;np++){            // nt pairs {0,1} and {2,3}
                    int rowb=wn*32+np*16+bq_row_off;
                    uint32_t off=rowb*128+kk*32+bq_k16*16;
                    off^=((off>>3)&0x70);
                    asm volatile("ldmatrix.sync.aligned.m8n8.x4.shared.b16 {%0,%1,%2,%3}, [%4];"
                        :"=r"(bf[np*2][0]),"=r"(bf[np*2][1]),"=r"(bf[np*2+1][0]),"=r"(bf[np*2+1][1])
                        :"r"(sB+off));
                }
#pragma unroll
                for(int mt=0;mt<2;mt++)
#pragma unroll
                    for(int nt2=0;nt2<4;nt2++)
                        asm volatile("mma.sync.aligned.m16n8k16.row.col.f32.bf16.bf16.f32 "
                            "{%0,%1,%2,%3}, {%4,%5,%6,%7}, {%8,%9}, {%0,%1,%2,%3};"
                            :"+f"(acc[mt][nt2][0]),"+f"(acc[mt][nt2][1]),"+f"(acc[mt][nt2][2]),"+f"(acc[mt][nt2][3])
                            :"r"(af[mt][0]),"r"(af[mt][1]),"r"(af[mt][2]),"r"(af[mt][3]),
                             "r"(bf[nt2][0]),"r"(bf[nt2][1]));
            }
            gbuf=(gbuf+1)&3;
        }

        int m0=(t/Nb)<<7, n0=(t-(t/Nb)*Nb)<<6;
#pragma unroll
        for(int mt=0;mt<2;mt++){
#pragma unroll
            for(int half=0;half<2;half++){
                int row=m0+wm*32+mt*16+(lane>>2)+half*8;
                int orow=(EPI==2)?win_src_row(row):row;
#pragma unroll
                for(int nt2=0;nt2<4;nt2++){
                    int col=n0+wn*32+nt2*8+(lane&3)*2;
                    float v0=acc[mt][nt2][half*2+0]+__ldg(bias+col);
                    float v1=acc[mt][nt2][half*2+1]+__ldg(bias+col+1);
                    if(EPI==1){ v0=gelu_exact(v0); v1=gelu_exact(v1); }
                    if(EPI==2||EPI==3){
                        const float* rp=res+(size_t)orow*N+col;
                        v0+=rp[0]; v1+=rp[1];
                    }
                    if(OUTBF){
                        *(uint32_t*)((__nv_bfloat16*)Cv+(size_t)orow*N+col)=bf2pack(v0,v1);
                    }else{
                        *(float2*)((float*)Cv+(size_t)orow*N+col)=make_float2(v0,v1);
                    }
                }
            }
        }
    }
}

// ---------------------------------------------------------------------------
// Attention: one block per window, 384 thr (6 heads x 64 rows), f32x2 FMA,
// single-pass softmax (scores tiny; mask -100 underflows exp -> 0).
// ---------------------------------------------------------------------------
#define ATTN_SMEM_BYTES 112256

__global__ __launch_bounds__(384)
void attn_kernel(const __nv_bfloat16* __restrict__ q, const __nv_bfloat16* __restrict__ kv,
                 const float* __restrict__ rpb, const float* __restrict__ mask,
                 __nv_bfloat16* __restrict__ ao){
    extern __shared__ char dsm[];
    unsigned long long* K8=(unsigned long long*)dsm;
    unsigned long long* V8=K8+64*96;
    __nv_bfloat16* Ms=(__nv_bfloat16*)(V8+64*96);
    float* Rp=(float*)(Ms+64*66);

    int win=blockIdx.x, tid=threadIdx.x;
    const __nv_bfloat162* kvb=(const __nv_bfloat162*)(kv+(size_t)win*64*384);
    for(int i=tid;i<64*192;i+=384){
        int row=i/192, p=i-row*192;
        float2 f=__bfloat1622float2(kvb[row*192+p]);
        unsigned long long pk;
        asm("mov.b64 %0,{%1,%2};":"=l"(pk):"r"(__float_as_uint(f.x)),"r"(__float_as_uint(f.y)));
        if(p<96) K8[row*96+p]=pk; else V8[row*96+p-96]=pk;
    }
    const float* mg=mask+(size_t)(win&511)*4096;
    for(int i=tid;i<4096;i+=384) Ms[(i>>6)*66+(i&63)]=__float2bfloat16(mg[i]);
    for(int i=tid;i<1350;i+=384) Rp[i]=rpb[i];

    int h=tid/64, t=tid-h*64;
    unsigned long long q2[16];
    {
        const __nv_bfloat162* qp=(const __nv_bfloat162*)(q+((size_t)win*64+t)*CDIM+h*HDIM);
        const float sc=0.17677669529663688f;
#pragma unroll
        for(int d=0;d<16;d++){
            float2 f=__bfloat1622float2(qp[d]);
            f.x*=sc; f.y*=sc;
            asm("mov.b64 %0,{%1,%2};":"=l"(q2[d]):"r"(__float_as_uint(f.x)),"r"(__float_as_uint(f.y)));
        }
    }
    __syncthreads();

    int i1=t>>3, j1=t&7, kb=h*16;
    unsigned long long od[16];
#pragma unroll
    for(int d=0;d<16;d++) od[d]=0ULL;
    float sum=0.0f;

    for(int m=0;m<64;m++){
        const unsigned long long* kp=K8+m*96+kb;
        unsigned long long a0=0,a1=0,a2=0,a3=0;
#pragma unroll
        for(int d=0;d<16;d+=4){
            asm("fma.rn.f32x2 %0, %1, %2, %0;":"+l"(a0):"l"(q2[d+0]),"l"(kp[d+0]));
            asm("fma.rn.f32x2 %0, %1, %2, %0;":"+l"(a1):"l"(q2[d+1]),"l"(kp[d+1]));
            asm("fma.rn.f32x2 %0, %1, %2, %0;":"+l"(a2):"l"(q2[d+2]),"l"(kp[d+2]));
            asm("fma.rn.f32x2 %0, %1, %2, %0;":"+l"(a3):"l"(q2[d+3]),"l"(kp[d+3]));
        }
        uint32_t lo,hi; float s;
        asm("mov.b64 {%0,%1}, %2;":"=r"(lo),"=r"(hi):"l"(a0)); s =__uint_as_float(lo)+__uint_as_float(hi);
        asm("mov.b64 {%0,%1}, %2;":"=r"(lo),"=r"(hi):"l"(a1)); s+=__uint_as_float(lo)+__uint_as_float(hi);
        asm("mov.b64 {%0,%1}, %2;":"=r"(lo),"=r"(hi):"l"(a2)); s+=__uint_as_float(lo)+__uint_as_float(hi);
        asm("mov.b64 {%0,%1}, %2;":"=r"(lo),"=r"(hi):"l"(a3)); s+=__uint_as_float(lo)+__uint_as_float(hi);

        int ridx=(i1-(m>>3)+7)*15+(j1-(m&7)+7);
        s += Rp[ridx*6+h] + __bfloat162float(Ms[t*66+m]);
        float e=__expf(s);
        sum+=e;
        unsigned long long e2;
        asm("mov.b64 %0,{%1,%1};":"=l"(e2):"r"(__float_as_uint(e)));
        const unsigned long long* vp=V8+m*96+kb;
#pragma unroll
        for(int d=0;d<16;d++)
            asm("fma.rn.f32x2 %0, %1, %2, %0;":"+l"(od[d]):"l"(e2),"l"(vp[d]));
    }
    float inv=1.0f/sum;
    __nv_bfloat162* orow=(__nv_bfloat162*)(ao+((size_t)win*64+t)*CDIM+h*HDIM);
#pragma unroll
    for(int d=0;d<16;d++){
        uint32_t lo,hi;
        asm("mov.b64 {%0,%1}, %2;":"=r"(lo),"=r"(hi):"l"(od[d]));
        orow[d]=__floats2bfloat162_rn(__uint_as_float(lo)*inv,__uint_as_float(hi)*inv);
    }
}

extern "C" void kernel_launch(void* const* d_in, const int* in_sizes, int n_in,
                              void* d_out, int out_size){
    const float* x     =(const float*)d_in[0];
    const float* x1    =(const float*)d_in[1];
    const float* mask  =(const float*)d_in[2];
    const float* n1g   =(const float*)d_in[3];
    const float* n1b   =(const float*)d_in[4];
    const float* q_w   =(const float*)d_in[5];
    const float* q_b   =(const float*)d_in[6];
    const float* kv_w  =(const float*)d_in[7];
    const float* kv_b  =(const float*)d_in[8];
    const float* rpb   =(const float*)d_in[9];
    const float* proj_w=(const float*)d_in[10];
    const float* proj_b=(const float*)d_in[11];
    const float* n2g   =(const float*)d_in[12];
    const float* n2b   =(const float*)d_in[13];
    const float* fc1_w =(const float*)d_in[14];
    const float* fc1_b =(const float*)d_in[15];
    const float* fc2_w =(const float*)d_in[16];
    const float* fc2_b =(const float*)d_in[17];

    __nv_bfloat16 *xw,*x1w,*qb,*kvb,*ao,*xn2,*hb,*wq,*wkv,*wp,*wf1,*wf2;
    float* xo;
    cudaGetSymbolAddress((void**)&xw, g_xw);  cudaGetSymbolAddress((void**)&x1w,g_x1w);
    cudaGetSymbolAddress((void**)&qb, g_qb);  cudaGetSymbolAddress((void**)&kvb,g_kvb);
    cudaGetSymbolAddress((void**)&ao, g_ao);  cudaGetSymbolAddress((void**)&xo, g_xo);
    cudaGetSymbolAddress((void**)&xn2,g_xn2); cudaGetSymbolAddress((void**)&hb, g_hb);
    cudaGetSymbolAddress((void**)&wq, g_wq);  cudaGetSymbolAddress((void**)&wkv,g_wkv);
    cudaGetSymbolAddress((void**)&wp, g_wp);  cudaGetSymbolAddress((void**)&wf1,g_wf1);
    cudaGetSymbolAddress((void**)&wf2,g_wf2);

    cudaFuncSetAttribute(gemm_mma<0,1>, cudaFuncAttributeMaxDynamicSharedMemorySize, GEMM_SMEM_BYTES);
    cudaFuncSetAttribute(gemm_mma<1,1>, cudaFuncAttributeMaxDynamicSharedMemorySize, GEMM_SMEM_BYTES);
    cudaFuncSetAttribute(gemm_mma<2,0>, cudaFuncAttributeMaxDynamicSharedMemorySize, GEMM_SMEM_BYTES);
    cudaFuncSetAttribute(gemm_mma<3,0>, cudaFuncAttributeMaxDynamicSharedMemorySize, GEMM_SMEM_BYTES);
    cudaFuncSetAttribute(attn_kernel,   cudaFuncAttributeMaxDynamicSharedMemorySize, ATTN_SMEM_BYTES);

    wt_transpose_all<<<(442368+255)/256,256>>>(q_w, kv_w, proj_w, fc1_w, fc2_w,
                                               wq, wkv, wp, wf1, wf2);

    ln1_gather_kernel<<<MROWS, CDIM>>>(x, x1, n1g, n1b, xw, x1w);

    gemm_mma<0,1><<<PGRID, 256, GEMM_SMEM_BYTES>>>(x1w, wq,  q_b,  nullptr, qb,  MROWS, CDIM,   CDIM);
    gemm_mma<0,1><<<PGRID, 256, GEMM_SMEM_BYTES>>>(xw,  wkv, kv_b, nullptr, kvb, MROWS, 2*CDIM, CDIM);

    attn_kernel<<<2048, 384, ATTN_SMEM_BYTES>>>(qb, kvb, rpb, mask, ao);

    gemm_mma<2,0><<<PGRID, 256, GEMM_SMEM_BYTES>>>(ao,  wp,  proj_b, x,  xo, MROWS, CDIM, CDIM);

    ln2_kernel<<<MROWS, CDIM>>>(xo, n2g, n2b, xn2);

    gemm_mma<1,1><<<PGRID, 256, GEMM_SMEM_BYTES>>>(xn2, wf1, fc1_b, nullptr, hb, MROWS, HIDDEN, CDIM);
    gemm_mma<3,0><<<PGRID, 256, GEMM_SMEM_BYTES>>>(hb,  wf2, fc2_b, xo, (float*)d_out, MROWS, CDIM, HIDDEN);
}

// round 17
// speedup vs baseline: 1.1521x; 1.1447x over previous
#include <cuda_runtime.h>
#include <cuda_bf16.h>
#include <cstdint>

#define HH 128
#define WW_ 256
#define CDIM 192
#define HDIM 32
#define HIDDEN 768
#define MROWS 131072
#define SHIFT 4
#define PGRID 304

__device__ __nv_bfloat16 g_xw [(size_t)MROWS*CDIM];
__device__ __nv_bfloat16 g_x1w[(size_t)MROWS*CDIM];
__device__ __nv_bfloat16 g_qb [(size_t)MROWS*CDIM];
__device__ __nv_bfloat16 g_kvb[(size_t)MROWS*2*CDIM];
__device__ __nv_bfloat16 g_ao [(size_t)MROWS*CDIM];
__device__ float         g_xo [(size_t)MROWS*CDIM];
__device__ __nv_bfloat16 g_xn2[(size_t)MROWS*CDIM];
__device__ __nv_bfloat16 g_hb [(size_t)MROWS*HIDDEN];
__device__ __nv_bfloat16 g_wq [CDIM*CDIM];
__device__ __nv_bfloat16 g_wkv[2*CDIM*CDIM];
__device__ __nv_bfloat16 g_wp [CDIM*CDIM];
__device__ __nv_bfloat16 g_wf1[HIDDEN*CDIM];
__device__ __nv_bfloat16 g_wf2[CDIM*HIDDEN];

__device__ __forceinline__ uint32_t smem_u32(const void* p){
    uint32_t r; asm("{ .reg .u64 t; cvta.to.shared.u64 t, %1; cvt.u32.u64 %0, t; }":"=r"(r):"l"(p)); return r;
}
__device__ __forceinline__ int win_src_row(int r){
    int b_=r>>6, t=r&63, b=b_>>9, wid=b_&511;
    int h=(((wid>>5)<<3)+(t>>3)+SHIFT)&(HH-1);
    int w=(((wid&31)<<3)+(t&7)+SHIFT)&(WW_-1);
    return (b<<15)+(h<<8)+w;
}
__device__ __forceinline__ float warp_sum(float v){
#pragma unroll
    for(int o=16;o>0;o>>=1) v+=__shfl_xor_sync(0xffffffffu,v,o);
    return v;
}
__device__ __forceinline__ float gelu_exact(float v){ return 0.5f*v*(1.0f+erff(v*0.70710678118654752f)); }
__device__ __forceinline__ uint32_t bf2pack(float lo,float hi){
    uint32_t r; asm("cvt.rn.bf16x2.f32 %0, %1, %2;":"=r"(r):"f"(hi),"f"(lo)); return r;
}
__device__ __forceinline__ void cp_async16(uint32_t dst, const void* src){
    asm volatile("cp.async.cg.shared.global [%0], [%1], 16;"::"r"(dst),"l"(src):"memory");
}
__device__ __forceinline__ void cp_commit(){ asm volatile("cp.async.commit_group;":::"memory"); }
template<int N> __device__ __forceinline__ void cp_wait(){ asm volatile("cp.async.wait_group %0;"::"n"(N):"memory"); }

// ---------------------------------------------------------------------------
// Fused weight prep
// ---------------------------------------------------------------------------
__global__ void wt_transpose_all(const float* __restrict__ q_w, const float* __restrict__ kv_w,
                                 const float* __restrict__ proj_w, const float* __restrict__ fc1_w,
                                 const float* __restrict__ fc2_w,
                                 __nv_bfloat16* __restrict__ wq, __nv_bfloat16* __restrict__ wkv,
                                 __nv_bfloat16* __restrict__ wp, __nv_bfloat16* __restrict__ wf1,
                                 __nv_bfloat16* __restrict__ wf2){
    int i = blockIdx.x*256+threadIdx.x;
    const float* s; __nv_bfloat16* d; int K, N;
    if      (i < 36864)  { s=q_w;    d=wq;  K=CDIM;   N=CDIM;   }
    else if (i < 110592) { s=kv_w;   d=wkv; K=CDIM;   N=2*CDIM; i-=36864;  }
    else if (i < 147456) { s=proj_w; d=wp;  K=CDIM;   N=CDIM;   i-=110592; }
    else if (i < 294912) { s=fc1_w;  d=wf1; K=CDIM;   N=HIDDEN; i-=147456; }
    else if (i < 442368) { s=fc2_w;  d=wf2; K=HIDDEN; N=CDIM;   i-=294912; }
    else return;
    int n=i/K, k=i-n*K;
    d[i] = __float2bfloat16(s[(size_t)k*N+n]);
}

__global__ void ln1_gather_kernel(const float* __restrict__ x, const float* __restrict__ x1,
                                  const float* __restrict__ g, const float* __restrict__ bb,
                                  __nv_bfloat16* __restrict__ xw, __nv_bfloat16* __restrict__ x1w){
    int r=blockIdx.x, src=win_src_row(r), t=threadIdx.x;
    float v0=x[(size_t)src*CDIM+t], v1=x1[(size_t)src*CDIM+t];
    float s0=warp_sum(v0), q0=warp_sum(v0*v0), s1=warp_sum(v1), q1=warp_sum(v1*v1);
    __shared__ float red[4][6];
    int wp=t>>5, ln=t&31;
    if(ln==0){ red[0][wp]=s0; red[1][wp]=q0; red[2][wp]=s1; red[3][wp]=q1; }
    __syncthreads();
    float S0=0,Q0=0,S1=0,Q1=0;
#pragma unroll
    for(int i=0;i<6;i++){ S0+=red[0][i]; Q0+=red[1][i]; S1+=red[2][i]; Q1+=red[3][i]; }
    const float inv=1.0f/CDIM;
    float m0=S0*inv, m1=S1*inv;
    float r0=rsqrtf(Q0*inv-m0*m0+1e-5f), r1=rsqrtf(Q1*inv-m1*m1+1e-5f);
    float gg=g[t], bv=bb[t];
    xw [(size_t)r*CDIM+t]=__float2bfloat16((v0-m0)*r0*gg+bv);
    x1w[(size_t)r*CDIM+t]=__float2bfloat16((v1-m1)*r1*gg+bv);
}

__global__ void ln2_kernel(const float* __restrict__ x, const float* __restrict__ g,
                           const float* __restrict__ bb, __nv_bfloat16* __restrict__ out){
    int r=blockIdx.x, t=threadIdx.x;
    float v=x[(size_t)r*CDIM+t];
    float s=warp_sum(v), q=warp_sum(v*v);
    __shared__ float red[2][6];
    int wp=t>>5, ln=t&31;
    if(ln==0){ red[0][wp]=s; red[1][wp]=q; }
    __syncthreads();
    float S=0,Q=0;
#pragma unroll
    for(int i=0;i<6;i++){ S+=red[0][i]; Q+=red[1][i]; }
    const float inv=1.0f/CDIM;
    float m=S*inv, rs=rsqrtf(Q*inv-m*m+1e-5f);
    out[(size_t)r*CDIM+t]=__float2bfloat16((v-m)*rs*g[t]+bb[t]);
}

// ---------------------------------------------------------------------------
// Persistent-streaming HMMA bf16 GEMM (R16 config, measured best family)
// ---------------------------------------------------------------------------
#define ABUF 16384
#define BUFB 24576
#define GEMM_SMEM_BYTES (4*BUFB + 1024)

template <int EPI, int OUTBF>
__global__ __launch_bounds__(256)
void gemm_mma(const __nv_bfloat16* __restrict__ A, const __nv_bfloat16* __restrict__ Bw,
              const float* __restrict__ bias, const float* __restrict__ res,
              void* __restrict__ Cv, int M, int N, int K){
    extern __shared__ char dsm[];
    uint32_t base = (smem_u32(dsm)+1023u)&~1023u;

    int tid=threadIdx.x, lane=tid&31, wid=tid>>5;
    int wm=wid&3, wn=wid>>2;
    int Nb=N>>6, nch=K>>6;
    int ntiles=(M>>7)*Nb;

    auto stage=[&](int buf,int m0,int n0,int k0){
        uint32_t sA=base+buf*BUFB, sB=sA+ABUF;
#pragma unroll
        for(int l=0;l<4;l++){
            int i=tid+l*256, rr=i>>3, cc=i&7;
            uint32_t off=rr*128+cc*16;
            cp_async16(sA+(off^((off>>3)&0x70)), A+(size_t)(m0+rr)*K+k0+cc*8);
        }
#pragma unroll
        for(int l=0;l<2;l++){
            int i=tid+l*256, rr=i>>3, cc=i&7;
            uint32_t off=rr*128+cc*16;
            cp_async16(sB+(off^((off>>3)&0x70)), Bw+(size_t)(n0+rr)*K+k0+cc*8);
        }
        cp_commit();
    };

    int t0=blockIdx.x;
    if(t0>=ntiles) return;

    int st_t=t0, st_c=0, st_buf=0;
    auto stage_next=[&](){
        if(st_t<ntiles){
            int mm=st_t/Nb, nn=st_t-mm*Nb;
            stage(st_buf, mm<<7, nn<<6, st_c<<6);
        } else cp_commit();
        st_buf=(st_buf+1)&3;
        if(++st_c==nch){ st_c=0; st_t+=PGRID; }
    };

    stage_next();
    stage_next();
    int gbuf=0;

    int bq_row_off = ((lane>>4)&1)*8 + (lane&7);
    int bq_k16     = (lane>>3)&1;

    for(int t=t0; t<ntiles; t+=PGRID){
        float acc[2][4][4];
#pragma unroll
        for(int a=0;a<2;a++)
#pragma unroll
            for(int b=0;b<4;b++)
#pragma unroll
                for(int c=0;c<4;c++) acc[a][b][c]=0.0f;

        for(int c=0;c<nch;c++){
            stage_next();
            cp_wait<2>();
            __syncthreads();

            uint32_t sA=base+gbuf*BUFB, sB=sA+ABUF;
#pragma unroll
            for(int kk=0;kk<4;kk++){
                uint32_t af[2][4];
#pragma unroll
                for(int mt=0;mt<2;mt++){
                    int row=wm*32+mt*16+(lane&15);
                    uint32_t off=row*128+kk*32+(lane>>4)*16;
                    off^=((off>>3)&0x70);
                    asm volatile("ldmatrix.sync.aligned.m8n8.x4.shared.b16 {%0,%1,%2,%3}, [%4];"
                        :"=r"(af[mt][0]),"=r"(af[mt][1]),"=r"(af[mt][2]),"=r"(af[mt][3]):"r"(sA+off));
                }
                uint32_t bf[4][2];
#pragma unroll
                for(int np=0;np<2;np++){
                    int rowb=wn*32+np*16+bq_row_off;
                    uint32_t off=rowb*128+kk*32+bq_k16*16;
                    off^=((off>>3)&0x70);
                    asm volatile("ldmatrix.sync.aligned.m8n8.x4.shared.b16 {%0,%1,%2,%3}, [%4];"
                        :"=r"(bf[np*2][0]),"=r"(bf[np*2][1]),"=r"(bf[np*2+1][0]),"=r"(bf[np*2+1][1])
                        :"r"(sB+off));
                }
#pragma unroll
                for(int mt=0;mt<2;mt++)
#pragma unroll
                    for(int nt2=0;nt2<4;nt2++)
                        asm volatile("mma.sync.aligned.m16n8k16.row.col.f32.bf16.bf16.f32 "
                            "{%0,%1,%2,%3}, {%4,%5,%6,%7}, {%8,%9}, {%0,%1,%2,%3};"
                            :"+f"(acc[mt][nt2][0]),"+f"(acc[mt][nt2][1]),"+f"(acc[mt][nt2][2]),"+f"(acc[mt][nt2][3])
                            :"r"(af[mt][0]),"r"(af[mt][1]),"r"(af[mt][2]),"r"(af[mt][3]),
                             "r"(bf[nt2][0]),"r"(bf[nt2][1]));
            }
            gbuf=(gbuf+1)&3;
        }

        int m0=(t/Nb)<<7, n0=(t-(t/Nb)*Nb)<<6;
#pragma unroll
        for(int mt=0;mt<2;mt++){
#pragma unroll
            for(int half=0;half<2;half++){
                int row=m0+wm*32+mt*16+(lane>>2)+half*8;
                int orow=(EPI==2)?win_src_row(row):row;
#pragma unroll
                for(int nt2=0;nt2<4;nt2++){
                    int col=n0+wn*32+nt2*8+(lane&3)*2;
                    float v0=acc[mt][nt2][half*2+0]+__ldg(bias+col);
                    float v1=acc[mt][nt2][half*2+1]+__ldg(bias+col+1);
                    if(EPI==1){ v0=gelu_exact(v0); v1=gelu_exact(v1); }
                    if(EPI==2||EPI==3){
                        const float* rp=res+(size_t)orow*N+col;
                        v0+=rp[0]; v1+=rp[1];
                    }
                    if(OUTBF){
                        *(uint32_t*)((__nv_bfloat16*)Cv+(size_t)orow*N+col)=bf2pack(v0,v1);
                    }else{
                        *(float2*)((float*)Cv+(size_t)orow*N+col)=make_float2(v0,v1);
                    }
                }
            }
        }
    }
}

// ---------------------------------------------------------------------------
// R17 tensor-core attention. One CTA per window, 384 thr = 12 warps (2/head).
// Phase 1: stage Q,K ([64 rows][400B], no swizzle, conflict-free stride),
//          V transposed ([192 dim rows][144B]), mask bf16, rpb.
// Phase 2: S = Q@K^T per head via mma (each warp m64n32k32), STS bf16.
// Phase 3: per-row softmax (scale+rpb+mask in fp32), P bf16 in place,
//          1/sum stored. Bank-rotated row reads (stride 37 words).
// Phase 4: out = P@V via mma (warp m32n32k64), write ao * (1/sum).
// ---------------------------------------------------------------------------
#define AQ_STR 400
#define AVT_STR 144
#define ASP_STR 144
#define OFF_K  25600
#define OFF_VT 51200
#define OFF_SP 78848
#define OFF_MS 134144
#define OFF_RP 142592
#define OFF_SI 147992
#define ATTN_SMEM_BYTES 149536

__global__ __launch_bounds__(384)
void attn_kernel(const __nv_bfloat16* __restrict__ q, const __nv_bfloat16* __restrict__ kv,
                 const float* __restrict__ rpb, const float* __restrict__ mask,
                 __nv_bfloat16* __restrict__ ao){
    extern __shared__ char dsm[];
    uint32_t sb = smem_u32(dsm);
    __nv_bfloat16* Ms = (__nv_bfloat16*)(dsm + OFF_MS);
    float* Rp  = (float*)(dsm + OFF_RP);
    float* Sinv= (float*)(dsm + OFF_SI);

    int win=blockIdx.x, tid=threadIdx.x;
    int lane=tid&31, wid=tid>>5;

    // ---- Phase 1: staging ----
    const __nv_bfloat16* kvw = kv + (size_t)win*64*384;
    const uint4* qsrc = (const uint4*)(q + (size_t)win*64*192);
    for(int i=tid;i<1536;i+=384){
        int r=i/24, j=i-r*24;
        *(uint4*)(dsm + r*AQ_STR + j*16) = qsrc[r*24+j];
        *(uint4*)(dsm + OFF_K + r*AQ_STR + j*16) = *(const uint4*)(kvw + (size_t)r*384 + j*8);
    }
    for(int i=tid;i<6144;i+=384){           // V^T: 64 tok x 96 dim-pairs
        int m=i/96, dp=i-m*96;
        uint32_t v = *(const uint32_t*)(kvw + (size_t)m*384 + 192 + dp*2);
        *(uint16_t*)(dsm + OFF_VT + (dp*2  )*AVT_STR + m*2) = (uint16_t)(v&0xffff);
        *(uint16_t*)(dsm + OFF_VT + (dp*2+1)*AVT_STR + m*2) = (uint16_t)(v>>16);
    }
    const float* mg = mask + (size_t)(win&511)*4096;
    for(int i=tid;i<4096;i+=384) Ms[(i>>6)*66+(i&63)] = __float2bfloat16(mg[i]);
    for(int i=tid;i<1350;i+=384) Rp[i]=rpb[i];
    __syncthreads();

    // ---- Phase 2: S = Q @ K^T ----
    int h = wid>>1, nh = wid&1, n0 = nh*32;
    {
        float acc[4][4][4];
#pragma unroll
        for(int a=0;a<4;a++)
#pragma unroll
            for(int b=0;b<4;b++)
#pragma unroll
                for(int c=0;c<4;c++) acc[a][b][c]=0.0f;
#pragma unroll
        for(int kk=0;kk<2;kk++){
            uint32_t af[4][4];
#pragma unroll
            for(int mt=0;mt<4;mt++){
                uint32_t a0=sb + (mt*16+(lane&15))*AQ_STR + h*64 + kk*32 + (lane>>4)*16;
                asm volatile("ldmatrix.sync.aligned.m8n8.x4.shared.b16 {%0,%1,%2,%3}, [%4];"
                    :"=r"(af[mt][0]),"=r"(af[mt][1]),"=r"(af[mt][2]),"=r"(af[mt][3]):"r"(a0));
            }
            uint32_t bfr[4][2];
#pragma unroll
            for(int nt=0;nt<4;nt++){
                uint32_t b0=sb + OFF_K + (n0+nt*8+(lane&7))*AQ_STR + h*64 + kk*32 + ((lane>>3)&1)*16;
                asm volatile("ldmatrix.sync.aligned.m8n8.x2.shared.b16 {%0,%1}, [%2];"
                    :"=r"(bfr[nt][0]),"=r"(bfr[nt][1]):"r"(b0));
            }
#pragma unroll
            for(int mt=0;mt<4;mt++)
#pragma unroll
                for(int nt=0;nt<4;nt++)
                    asm volatile("mma.sync.aligned.m16n8k16.row.col.f32.bf16.bf16.f32 "
                        "{%0,%1,%2,%3}, {%4,%5,%6,%7}, {%8,%9}, {%0,%1,%2,%3};"
                        :"+f"(acc[mt][nt][0]),"+f"(acc[mt][nt][1]),"+f"(acc[mt][nt][2]),"+f"(acc[mt][nt][3])
                        :"r"(af[mt][0]),"r"(af[mt][1]),"r"(af[mt][2]),"r"(af[mt][3]),
                         "r"(bfr[nt][0]),"r"(bfr[nt][1]));
        }
        // store S (bf16) to SP[h]
#pragma unroll
        for(int mt=0;mt<4;mt++)
#pragma unroll
            for(int nt=0;nt<4;nt++){
                int col=n0+nt*8+(lane&3)*2;
                int r0=mt*16+(lane>>2);
                *(uint32_t*)(dsm + OFF_SP + h*9216 + r0*ASP_STR + col*2) = bf2pack(acc[mt][nt][0],acc[mt][nt][1]);
                *(uint32_t*)(dsm + OFF_SP + h*9216 + (r0+8)*ASP_STR + col*2) = bf2pack(acc[mt][nt][2],acc[mt][nt][3]);
            }
    }
    __syncthreads();

    // ---- Phase 3: softmax (thread = (head h2, row t)) ----
    {
        int h2=tid/64, t=tid-h2*64;
        int i1=t>>3, j1=t&7;
        uint32_t* Sp32=(uint32_t*)(dsm + OFF_SP + h2*9216 + t*ASP_STR);
        const float scale=0.17677669529663688f;
        float sum=0.0f;
#pragma unroll 4
        for(int p0=0;p0<32;p0++){
            int p=(p0+t)&31;
            uint32_t pk=Sp32[p];
            float2 f=__bfloat1622float2(*(__nv_bfloat162*)&pk);
            int m0=2*p, m1=m0+1;
            int r0=(i1-(m0>>3)+7)*15+(j1-(m0&7)+7);
            int r1=(i1-(m1>>3)+7)*15+(j1-(m1&7)+7);
            float s0=f.x*scale + Rp[r0*6+h2] + __bfloat162float(Ms[t*66+m0]);
            float s1=f.y*scale + Rp[r1*6+h2] + __bfloat162float(Ms[t*66+m1]);
            float e0=__expf(s0), e1=__expf(s1);
            sum+=e0+e1;
            Sp32[p]=bf2pack(e0,e1);
        }
        Sinv[h2*64+t]=1.0f/sum;
    }
    __syncthreads();

    // ---- Phase 4: out = P @ V ----
    {
        int half=nh;                        // warp's M-half (rows half*32..+31)
        float acc[2][4][4];
#pragma unroll
        for(int a=0;a<2;a++)
#pragma unroll
            for(int b=0;b<4;b++)
#pragma unroll
                for(int c=0;c<4;c++) acc[a][b][c]=0.0f;
#pragma unroll
        for(int kk=0;kk<4;kk++){
            uint32_t af[2][4];
#pragma unroll
            for(int mt=0;mt<2;mt++){
                uint32_t a0=sb + OFF_SP + h*9216 + (half*32+mt*16+(lane&15))*ASP_STR + kk*32 + (lane>>4)*16;
                asm volatile("ldmatrix.sync.aligned.m8n8.x4.shared.b16 {%0,%1,%2,%3}, [%4];"
                    :"=r"(af[mt][0]),"=r"(af[mt][1]),"=r"(af[mt][2]),"=r"(af[mt][3]):"r"(a0));
            }
            uint32_t bfr[4][2];
#pragma unroll
            for(int nt=0;nt<4;nt++){
                uint32_t b0=sb + OFF_VT + (h*32+nt*8+(lane&7))*AVT_STR + kk*32 + ((lane>>3)&1)*16;
                asm volatile("ldmatrix.sync.aligned.m8n8.x2.shared.b16 {%0,%1}, [%2];"
                    :"=r"(bfr[nt][0]),"=r"(bfr[nt][1]):"r"(b0));
            }
#pragma unroll
            for(int mt=0;mt<2;mt++)
#pragma unroll
                for(int nt=0;nt<4;nt++)
                    asm volatile("mma.sync.aligned.m16n8k16.row.col.f32.bf16.bf16.f32 "
                        "{%0,%1,%2,%3}, {%4,%5,%6,%7}, {%8,%9}, {%0,%1,%2,%3};"
                        :"+f"(acc[mt][nt][0]),"+f"(acc[mt][nt][1]),"+f"(acc[mt][nt][2]),"+f"(acc[mt][nt][3])
                        :"r"(af[mt][0]),"r"(af[mt][1]),"r"(af[mt][2]),"r"(af[mt][3]),
                         "r"(bfr[nt][0]),"r"(bfr[nt][1]));
        }
#pragma unroll
        for(int mt=0;mt<2;mt++)
#pragma unroll
            for(int h2f=0;h2f<2;h2f++){
                int row=half*32+mt*16+(lane>>2)+h2f*8;
                float inv=Sinv[h*64+row];
#pragma unroll
                for(int nt=0;nt<4;nt++){
                    int col=nt*8+(lane&3)*2;
                    *(uint32_t*)(ao + ((size_t)win*64+row)*CDIM + h*HDIM + col)
                        = bf2pack(acc[mt][nt][h2f*2+0]*inv, acc[mt][nt][h2f*2+1]*inv);
                }
            }
    }
}

extern "C" void kernel_launch(void* const* d_in, const int* in_sizes, int n_in,
                              void* d_out, int out_size){
    const float* x     =(const float*)d_in[0];
    const float* x1    =(const float*)d_in[1];
    const float* mask  =(const float*)d_in[2];
    const float* n1g   =(const float*)d_in[3];
    const float* n1b   =(const float*)d_in[4];
    const float* q_w   =(const float*)d_in[5];
    const float* q_b   =(const float*)d_in[6];
    const float* kv_w  =(const float*)d_in[7];
    const float* kv_b  =(const float*)d_in[8];
    const float* rpb   =(const float*)d_in[9];
    const float* proj_w=(const float*)d_in[10];
    const float* proj_b=(const float*)d_in[11];
    const float* n2g   =(const float*)d_in[12];
    const float* n2b   =(const float*)d_in[13];
    const float* fc1_w =(const float*)d_in[14];
    const float* fc1_b =(const float*)d_in[15];
    const float* fc2_w =(const float*)d_in[16];
    const float* fc2_b =(const float*)d_in[17];

    __nv_bfloat16 *xw,*x1w,*qb,*kvb,*ao,*xn2,*hb,*wq,*wkv,*wp,*wf1,*wf2;
    float* xo;
    cudaGetSymbolAddress((void**)&xw, g_xw);  cudaGetSymbolAddress((void**)&x1w,g_x1w);
    cudaGetSymbolAddress((void**)&qb, g_qb);  cudaGetSymbolAddress((void**)&kvb,g_kvb);
    cudaGetSymbolAddress((void**)&ao, g_ao);  cudaGetSymbolAddress((void**)&xo, g_xo);
    cudaGetSymbolAddress((void**)&xn2,g_xn2); cudaGetSymbolAddress((void**)&hb, g_hb);
    cudaGetSymbolAddress((void**)&wq, g_wq);  cudaGetSymbolAddress((void**)&wkv,g_wkv);
    cudaGetSymbolAddress((void**)&wp, g_wp);  cudaGetSymbolAddress((void**)&wf1,g_wf1);
    cudaGetSymbolAddress((void**)&wf2,g_wf2);

    cudaFuncSetAttribute(gemm_mma<0,1>, cudaFuncAttributeMaxDynamicSharedMemorySize, GEMM_SMEM_BYTES);
    cudaFuncSetAttribute(gemm_mma<1,1>, cudaFuncAttributeMaxDynamicSharedMemorySize, GEMM_SMEM_BYTES);
    cudaFuncSetAttribute(gemm_mma<2,0>, cudaFuncAttributeMaxDynamicSharedMemorySize, GEMM_SMEM_BYTES);
    cudaFuncSetAttribute(gemm_mma<3,0>, cudaFuncAttributeMaxDynamicSharedMemorySize, GEMM_SMEM_BYTES);
    cudaFuncSetAttribute(attn_kernel,   cudaFuncAttributeMaxDynamicSharedMemorySize, ATTN_SMEM_BYTES);

    wt_transpose_all<<<(442368+255)/256,256>>>(q_w, kv_w, proj_w, fc1_w, fc2_w,
                                               wq, wkv, wp, wf1, wf2);

    ln1_gather_kernel<<<MROWS, CDIM>>>(x, x1, n1g, n1b, xw, x1w);

    gemm_mma<0,1><<<PGRID, 256, GEMM_SMEM_BYTES>>>(x1w, wq,  q_b,  nullptr, qb,  MROWS, CDIM,   CDIM);
    gemm_mma<0,1><<<PGRID, 256, GEMM_SMEM_BYTES>>>(xw,  wkv, kv_b, nullptr, kvb, MROWS, 2*CDIM, CDIM);

    attn_kernel<<<2048, 384, ATTN_SMEM_BYTES>>>(qb, kvb, rpb, mask, ao);

    gemm_mma<2,0><<<PGRID, 256, GEMM_SMEM_BYTES>>>(ao,  wp,  proj_b, x,  xo, MROWS, CDIM, CDIM);

    ln2_kernel<<<MROWS, CDIM>>>(xo, n2g, n2b, xn2);

    gemm_mma<1,1><<<PGRID, 256, GEMM_SMEM_BYTES>>>(xn2, wf1, fc1_b, nullptr, hb, MROWS, HIDDEN, CDIM);
    gemm_mma<3,0><<<PGRID, 256, GEMM_SMEM_BYTES>>>(hb,  wf2, fc2_b, xo, (float*)d_out, MROWS, CDIM, HIDDEN);
}